// round 11
// baseline (speedup 1.0000x reference)
#include <cuda_runtime.h>
#include <cuda_bf16.h>
#include <math.h>

#define H_  80
#define W_  80
#define HW  6400
#define C_  256
#define CP  19
#define KS  7
#define K2  49

// Scratch (allocation-free: __device__ globals)
__device__ float g_bias[C_];           // BN-folded bias for w_feat
__device__ float g_wa1[C_ * C_];       // fragment-ordered BN-folded w_feat
__device__ float g_wa2[C_ * C_];       // fragment-ordered w_fuse
__device__ unsigned g_msgpk[128 * HW]; // messages, bf16x2 channel pairs
__device__ float g_agg[C_ * HW];       // aggregated (fp32)
__device__ float g_aff[K2 * HW];       // unnormalized affinity exp(exp(-d/denom))

// ---------------------------------------------------------------------------
// Front kernel: blockIdx-partitioned union of
//   [0,140)      affinity taps (20 x 7 layout, 160 thr = 40 px * 4 rows)
//   [140,1164)   weight rearrange (BN scale folded into w_feat)
//   [1164,1420)  BN-folded bias reduction
// Fragment order: [kb 0..31][mb 0..15][lane][a0..a3].
// ---------------------------------------------------------------------------
__global__ void __launch_bounds__(160) front_kernel(
        const float* __restrict__ coarse, const float* __restrict__ sigma,
        const float* __restrict__ wfeat,  const float* __restrict__ wfuse,
        const float* __restrict__ gamma,  const float* __restrict__ beta,
        const float* __restrict__ mean,   const float* __restrict__ var) {
    int b = blockIdx.x;
    int t = threadIdx.x;

    if (b < 140) {
        // ---- affinity: 2 pixels per thread, sliding window ----
        int tx = t % 40;                  // 0..39 -> pixels 2tx, 2tx+1
        int h  = (b % 20) * 4 + t / 40;
        int i  = b / 20;                  // tap row 0..6
        int b0 = tx * 2;

        float sr = fmaxf(sigma[0], 0.0f);
        float invd = 1.0f / (2.0f * sr * sr + 1e-8f);

        int hh = h + i - 3;
        bool rowok = (hh >= 0) && (hh < H_);
        const float* crow = coarse + h * W_;
        const float* nrow = coarse + (rowok ? hh : 0) * W_;

        bool v[5];
#pragma unroll
        for (int l = 0; l < 5; l++) {
            int col = b0 - 4 + 2 * l;
            v[l] = rowok && (col >= 0) && (col <= W_ - 2);
        }

        float d[KS][2];
#pragma unroll
        for (int j = 0; j < KS; j++) { d[j][0] = 0.0f; d[j][1] = 0.0f; }

        const float2 z2 = make_float2(0.0f, 0.0f);
#pragma unroll
        for (int cp = 0; cp < CP; cp++) {
            float2 cen = *(const float2*)(crow + cp * HW + b0);
            const float* nb = nrow + cp * HW;
            float win[8];
            float2 L;
            L = v[0] ? *(const float2*)(nb + b0 - 4) : z2; win[0] = L.y;
            L = v[1] ? *(const float2*)(nb + b0 - 2) : z2; win[1] = L.x; win[2] = L.y;
            L = v[2] ? *(const float2*)(nb + b0)     : z2; win[3] = L.x; win[4] = L.y;
            L = v[3] ? *(const float2*)(nb + b0 + 2) : z2; win[5] = L.x; win[6] = L.y;
            L = v[4] ? *(const float2*)(nb + b0 + 4) : z2; win[7] = L.x;
#pragma unroll
            for (int j = 0; j < KS; j++) {
                float t0 = win[j]     - cen.x; d[j][0] += t0 * t0;
                float t1 = win[j + 1] - cen.y; d[j][1] += t1 * t1;
            }
        }

        int p = h * W_ + b0;
#pragma unroll
        for (int j = 0; j < KS; j++) {
            g_aff[(i * KS + j) * HW + p]     = __expf(__expf(-d[j][0] * invd));
            g_aff[(i * KS + j) * HW + p + 1] = __expf(__expf(-d[j][1] * invd));
        }
    } else if (b < 1164) {
        // ---- weight rearrange ----
        if (t < 128) {
            int bb = b - 140;
            int w2 = bb >> 9;             // 0: wfeat (scaled), 1: wfuse
            bb &= 511;
            int kb = bb & 31, mb = bb >> 5;
            int lane = t & 31, q = t >> 5;
            int gid = lane >> 2, tig = lane & 3;
            int row = mb * 16 + gid + (q & 1) * 8;
            int col = kb * 8 + tig + (q >> 1) * 4;
            const float* src = w2 ? wfuse : wfeat;
            float v = src[row * C_ + col];
            if (!w2) v *= gamma[col] * rsqrtf(var[col] + 1e-5f);
            float* dst = w2 ? g_wa2 : g_wa1;
            dst[((kb * 16 + mb) * 32 + lane) * 4 + q] = v;
        }
    } else {
        // ---- bias reduction ----
        int o = b - 1164;                 // 0..255
        float s = 0.0f;
        for (int c = t; c < C_; c += 160) {
            float a = gamma[c] * rsqrtf(var[c] + 1e-5f);
            s += wfeat[o * C_ + c] * (beta[c] - mean[c] * a);
        }
#pragma unroll
        for (int off = 16; off; off >>= 1) s += __shfl_xor_sync(~0u, s, off);
        __shared__ float red[5];
        if ((t & 31) == 0) red[t >> 5] = s;
        __syncthreads();
        if (t == 0) g_bias[o] = red[0] + red[1] + red[2] + red[3] + red[4];
    }
}

// ---------------------------------------------------------------------------
// Tensor-core GEMM (tf32 mma.sync), BARRIER-FREE MAINLOOP.
// Tile 128x64. The block's full B panel [K=256][64] is cp.async'd into
// dynamic smem ONCE (one wait + one syncthreads); the 32 k8-steps then run
// with no synchronization at all — warps slip freely to hide LDG/LDS latency.
// 8 warps (2x4), warp tile 64x16 (4 mi x 2 ni frags). Grid 100x2.
// ---------------------------------------------------------------------------
#define GBN 64
#define BSTR (GBN + 8)      // 72: LDS frag bank = 8*tig+gid, conflict-free
#define BPANEL_BYTES (C_ * BSTR * 4)   // 73728

__device__ __forceinline__ void cp16(void* smem, const void* gmem) {
    unsigned s = (unsigned)__cvta_generic_to_shared(smem);
    asm volatile("cp.async.ca.shared.global [%0], [%1], 16;\n" :: "r"(s), "l"(gmem));
}

__device__ __forceinline__ void mma_tf32(float* c, const unsigned* a, const unsigned* b) {
    asm volatile(
        "mma.sync.aligned.m16n8k8.row.col.f32.tf32.tf32.f32 "
        "{%0,%1,%2,%3}, {%4,%5,%6,%7}, {%8,%9}, {%0,%1,%2,%3};\n"
        : "+f"(c[0]), "+f"(c[1]), "+f"(c[2]), "+f"(c[3])
        : "r"(a[0]), "r"(a[1]), "r"(a[2]), "r"(a[3]), "r"(b[0]), "r"(b[1]));
}

__global__ void __launch_bounds__(256) gemm_tc(
        const float* __restrict__ Afrag,   // fragment-ordered [32][16][32][4]
        const float* __restrict__ B,       // [C_ x HW]
        float* __restrict__ Cout,          // used when msgpk == null
        unsigned* __restrict__ msgpk,      // packed output (or null)
        const float* __restrict__ bias,
        const float* __restrict__ resid) {
    extern __shared__ __align__(16) float Bs_raw[];
    float (*Bs)[BSTR] = (float(*)[BSTR])Bs_raw;
    const int N = HW;

    int t    = threadIdx.x;
    int warp = t >> 5, lane = t & 31;
    int gid  = lane >> 2, tig = lane & 3;
    int wm   = warp >> 2, wn = warp & 3;      // 2 x 4 warps
    int m0   = blockIdx.y * 128, n0 = blockIdx.x * GBN;
    int mbw  = (m0 >> 4) + wm * 4;            // warp's base 16-row block

    // ---- one-shot B panel load: 256 rows x 64 cols = 4096 16B chunks ----
#pragma unroll
    for (int i = 0; i < 16; i++) {
        int c = t + 256 * i;
        int row = c >> 4, cq = (c & 15) * 4;
        cp16(&Bs[row][cq], B + row * N + n0 + cq);
    }
    asm volatile("cp.async.commit_group;\n");

    float acc[4][2][4];
#pragma unroll
    for (int mi = 0; mi < 4; mi++)
#pragma unroll
        for (int ni = 0; ni < 2; ni++)
#pragma unroll
            for (int q = 0; q < 4; q++) acc[mi][ni][q] = 0.0f;

    asm volatile("cp.async.wait_group 0;\n");
    __syncthreads();
    // ---- mainloop: 32 k8-steps, NO barriers ----
    const float* abase = Afrag + lane * 4;
    int cN0 = wn * 16 + gid;
#pragma unroll 4
    for (int ks = 0; ks < 32; ks++) {
        unsigned aR[4][4];
#pragma unroll
        for (int mi = 0; mi < 4; mi++) {
            float4 a = *(const float4*)(abase + (ks * 16 + mbw + mi) * 128);
            aR[mi][0] = __float_as_uint(a.x);
            aR[mi][1] = __float_as_uint(a.y);
            aR[mi][2] = __float_as_uint(a.z);
            aR[mi][3] = __float_as_uint(a.w);
        }
        unsigned bR[2][2];
#pragma unroll
        for (int ni = 0; ni < 2; ni++) {
            bR[ni][0] = __float_as_uint(Bs[ks * 8 + tig][cN0 + ni * 8]);
            bR[ni][1] = __float_as_uint(Bs[ks * 8 + tig + 4][cN0 + ni * 8]);
        }
#pragma unroll
        for (int mi = 0; mi < 4; mi++)
#pragma unroll
            for (int ni = 0; ni < 2; ni++)
                mma_tf32(acc[mi][ni], aR[mi], bR[ni]);
    }

    // ---- epilogue ----
#pragma unroll
    for (int mi = 0; mi < 4; mi++) {
        int r0 = (mbw + mi) * 16 + gid;
        int r1 = r0 + 8;
        float b0v = bias ? bias[r0] : 0.0f;
        float b1v = bias ? bias[r1] : 0.0f;
#pragma unroll
        for (int ni = 0; ni < 2; ni++) {
            int col = n0 + wn * 16 + ni * 8 + tig * 2;
            float2 v0, v1;
            v0.x = acc[mi][ni][0] + b0v;
            v0.y = acc[mi][ni][1] + b0v;
            v1.x = acc[mi][ni][2] + b1v;
            v1.y = acc[mi][ni][3] + b1v;
            if (msgpk) {
                int pid = (mbw + mi) * 8 + gid;   // pairs rows (r0, r0+8)
                __nv_bfloat162 w0 = __floats2bfloat162_rn(v0.x, v1.x);
                __nv_bfloat162 w1 = __floats2bfloat162_rn(v0.y, v1.y);
                uint2 pk;
                pk.x = *reinterpret_cast<unsigned*>(&w0);
                pk.y = *reinterpret_cast<unsigned*>(&w1);
                *(uint2*)(msgpk + pid * N + col) = pk;
            } else {
                if (resid) {
                    float2 rv0 = *(const float2*)(resid + r0 * N + col);
                    float2 rv1 = *(const float2*)(resid + r1 * N + col);
                    v0.x += rv0.x; v0.y += rv0.y;
                    v1.x += rv1.x; v1.y += rv1.y;
                }
                *(float2*)(Cout + r0 * N + col) = v0;
                *(float2*)(Cout + r1 * N + col) = v1;
            }
        }
    }
}

// ---------------------------------------------------------------------------
// Aggregation: 4 pixels x 2 channel-pairs per thread.
// Block (20,16)=320 thr, grid (80,4). bf16x2 unpack is exact (<<16).
// ---------------------------------------------------------------------------
__global__ void __launch_bounds__(320) agg_kernel() {
    int h  = blockIdx.x;                       // 0..79
    int tx = threadIdx.x;                      // 0..19 -> pixels 4tx..4tx+3
    int ty = threadIdx.y;                      // 0..15
    int pbase = blockIdx.y * 32 + ty * 2;      // 2 pairs per thread

    __shared__ __align__(16) float saff[K2][W_];
    __shared__ __align__(16) float sinv[W_];
    int tid = ty * 20 + tx;
    const float* affrow = g_aff + h * W_;
    for (int idx = tid; idx < K2 * W_; idx += 320) {
        int k2 = idx / W_;
        int ww = idx - k2 * W_;
        saff[k2][ww] = affrow[k2 * HW + ww];
    }
    __syncthreads();
    if (tid < W_) {
        float s = 0.0f;
#pragma unroll
        for (int k = 0; k < K2; k++) s += saff[k][tid];
        sinv[tid] = 1.0f / s;
    }
    __syncthreads();

    float2 acc[4][2];   // [px][pair]: x = low channel, y = high channel
#pragma unroll
    for (int px = 0; px < 4; px++)
#pragma unroll
        for (int pr = 0; pr < 2; pr++) acc[px][pr] = make_float2(0.f, 0.f);

    const uint4 z4 = make_uint4(0u, 0u, 0u, 0u);
    bool haveA = (tx > 0), haveC = (tx < 19);

    for (int i = 0; i < KS; i++) {
        int hh = h + i - 3;
        if (hh < 0 || hh >= H_) continue;

        float4 s[KS];
#pragma unroll
        for (int j = 0; j < KS; j++)
            s[j] = *(const float4*)&saff[i * KS + j][tx * 4];

#pragma unroll
        for (int pr = 0; pr < 2; pr++) {
            const unsigned* mrow = g_msgpk + (pbase + pr) * HW + hh * W_;
            uint4 va = haveA ? *(const uint4*)(mrow + tx * 4 - 4) : z4;
            uint4 vb = *(const uint4*)(mrow + tx * 4);
            uint4 vc = haveC ? *(const uint4*)(mrow + tx * 4 + 4) : z4;
            unsigned wd[10] = {va.y, va.z, va.w,
                               vb.x, vb.y, vb.z, vb.w,
                               vc.x, vc.y, vc.z};
            float wl[10], wh[10];
#pragma unroll
            for (int q = 0; q < 10; q++) {
                wl[q] = __uint_as_float(wd[q] << 16);
                wh[q] = __uint_as_float(wd[q] & 0xFFFF0000u);
            }
#pragma unroll
            for (int j = 0; j < KS; j++) {
                acc[0][pr].x += wl[j + 0] * s[j].x;
                acc[0][pr].y += wh[j + 0] * s[j].x;
                acc[1][pr].x += wl[j + 1] * s[j].y;
                acc[1][pr].y += wh[j + 1] * s[j].y;
                acc[2][pr].x += wl[j + 2] * s[j].z;
                acc[2][pr].y += wh[j + 2] * s[j].z;
                acc[3][pr].x += wl[j + 3] * s[j].w;
                acc[3][pr].y += wh[j + 3] * s[j].w;
            }
        }
    }

    float4 si = *(const float4*)&sinv[tx * 4];
#pragma unroll
    for (int pr = 0; pr < 2; pr++) {
        int pid = pbase + pr;
        int c0 = (pid >> 3) * 16 + (pid & 7);
        int c1 = c0 + 8;
        float4 lo = make_float4(acc[0][pr].x * si.x, acc[1][pr].x * si.y,
                                acc[2][pr].x * si.z, acc[3][pr].x * si.w);
        float4 hi = make_float4(acc[0][pr].y * si.x, acc[1][pr].y * si.y,
                                acc[2][pr].y * si.z, acc[3][pr].y * si.w);
        *(float4*)(g_agg + c0 * HW + h * W_ + tx * 4) = lo;
        *(float4*)(g_agg + c1 * HW + h * W_ + tx * 4) = hi;
    }
}

// ---------------------------------------------------------------------------
// Launch
// ---------------------------------------------------------------------------
extern "C" void kernel_launch(void* const* d_in, const int* in_sizes, int n_in,
                              void* d_out, int out_size) {
    const float* x      = (const float*)d_in[0];
    const float* coarse = (const float*)d_in[1];
    const float* sigma  = (const float*)d_in[2];
    const float* wfeat  = (const float*)d_in[3];
    const float* wfuse  = (const float*)d_in[4];
    const float* gamma  = (const float*)d_in[5];
    const float* beta   = (const float*)d_in[6];
    const float* mean   = (const float*)d_in[7];
    const float* var    = (const float*)d_in[8];
    float* out = (float*)d_out;

    float *wa1, *wa2, *bias, *agg;
    unsigned* msgpk;
    cudaGetSymbolAddress((void**)&wa1,   g_wa1);
    cudaGetSymbolAddress((void**)&wa2,   g_wa2);
    cudaGetSymbolAddress((void**)&bias,  g_bias);
    cudaGetSymbolAddress((void**)&msgpk, g_msgpk);
    cudaGetSymbolAddress((void**)&agg,   g_agg);

    cudaFuncSetAttribute(gemm_tc,
        cudaFuncAttributeMaxDynamicSharedMemorySize, BPANEL_BYTES);

    // affinity taps + weight rearrange + bias, one launch
    front_kernel<<<1420, 160>>>(coarse, sigma, wfeat, wfuse,
                                gamma, beta, mean, var);
    // messages = w' @ x + bias  (packed bf16x2 channel-pair output)
    gemm_tc<<<dim3(HW / GBN, 2), 256, BPANEL_BYTES>>>(
        wa1, x, nullptr, msgpk, bias, nullptr);
    // spatially-varying 7x7 aggregation with fused softmax normalization
    agg_kernel<<<dim3(H_, C_ / 64), dim3(20, 16)>>>();
    // out = x + w_fuse @ agg
    gemm_tc<<<dim3(HW / GBN, 2), 256, BPANEL_BYTES>>>(
        wa2, agg, out, nullptr, nullptr, x);
}